// round 16
// baseline (speedup 1.0000x reference)
// R16: R15 base + 16-edge gather chunks (2x MLP window) + fused cvt/deg prologue.
#include <cuda_runtime.h>
#include <cuda_fp16.h>
#include <math.h>
#include <float.h>

#define NN 100000
#define EE 1200000
#define FD 64
#define NG 1024
#define NT 12
#define CHID 128
#define EPS 1e-5f
#define NB1 98   // (NN+1023)/1024

#define HS 72                    // half-tile row stride (halves)
#define TILE_H (64 * HS)         // halves per tile
#define SMEM_L (6 * TILE_H * 2)  // 6 half-tiles = 55296 B dynamic smem

// ---------------- scratch ----------------
__device__ __half g_xh[(size_t)NN * FD];   // fp16 feats (layer-1 gather source)
__device__ __half g_h1h[(size_t)NN * FD];  // fp16 h1 (layer-2 gather source)
__device__ float g_h1[(size_t)NN * FD];
__device__ float g_h2[(size_t)NN * FD];
__device__ float g_w[NN];
__device__ int   g_deg[NN + 1];
__device__ int   g_off[NN + 1];
__device__ int   g_cur[NN];
__device__ int   g_esrc[EE];
__device__ int   g_bsum[128];
__device__ int   g_bpre[128];
__device__ float g_stats1[2 * FD];
__device__ float g_stats2[2 * FD];
__device__ float g_statsC[2 * CHID];
__device__ float g_hg[(size_t)NG * 2 * FD];
__device__ float g_z[(size_t)NG * CHID];

// ---------------- zero ----------------
__global__ void k_zero() {
    int i = blockIdx.x * blockDim.x + threadIdx.x;
    if (i < NN + 1) g_deg[i] = 0;
    if (i < NN) g_cur[i] = 0;
    if (i < 2 * FD) { g_stats1[i] = 0.f; g_stats2[i] = 0.f; }
    if (i < 2 * CHID) g_statsC[i] = 0.f;
}

// ---------------- fused prologue: feats->fp16 convert + degree count ----------------
__global__ void k_pre(const float* __restrict__ x, __half* __restrict__ o,
                      const int* __restrict__ dst) {
    int i = blockIdx.x * blockDim.x + threadIdx.x;
    if (i < NN * FD / 4) {
        float4 v = ((const float4*)x)[i];
        __half2 a = __floats2half2_rn(v.x, v.y);
        __half2 b = __floats2half2_rn(v.z, v.w);
        ((uint2*)o)[i] = make_uint2(*(unsigned*)&a, *(unsigned*)&b);
    }
    if (i < EE / 4) {
        int4 d = ((const int4*)dst)[i];
        atomicAdd(&g_deg[d.x], 1);
        atomicAdd(&g_deg[d.y], 1);
        atomicAdd(&g_deg[d.z], 1);
        atomicAdd(&g_deg[d.w], 1);
    }
}

__global__ __launch_bounds__(1024) void k_scan1() {
    int tid = threadIdx.x;
    int i = blockIdx.x * 1024 + tid;
    int d = (i < NN) ? g_deg[i] : 0;
    int lane = tid & 31, wid = tid >> 5;
    int v = d;
    #pragma unroll
    for (int o = 1; o < 32; o <<= 1) {
        int t = __shfl_up_sync(0xffffffffu, v, o);
        if (lane >= o) v += t;
    }
    __shared__ int ws[32];
    if (lane == 31) ws[wid] = v;
    __syncthreads();
    if (wid == 0) {
        int u = ws[lane];
        #pragma unroll
        for (int o = 1; o < 32; o <<= 1) {
            int t = __shfl_up_sync(0xffffffffu, u, o);
            if (lane >= o) u += t;
        }
        ws[lane] = u;
    }
    __syncthreads();
    int base = wid ? ws[wid - 1] : 0;
    if (i < NN) g_off[i] = base + v - d;
    if (tid == 0) g_bsum[blockIdx.x] = ws[31];
}

__global__ void k_scan2() {
    __shared__ int sh[128];
    int tid = threadIdx.x;
    int v = (tid < NB1) ? g_bsum[tid] : 0;
    sh[tid] = v;
    __syncthreads();
    for (int o = 1; o < 128; o <<= 1) {
        int t = (tid >= o) ? sh[tid - o] : 0;
        __syncthreads();
        sh[tid] += t;
        __syncthreads();
    }
    if (tid < NB1) g_bpre[tid] = sh[tid] - v;
}

__global__ void k_scatter(const int* __restrict__ src, const int* __restrict__ dst) {
    int i = blockIdx.x * blockDim.x + threadIdx.x;
    if (i < EE / 4) {
        int4 s = ((const int4*)src)[i];
        int4 d = ((const int4*)dst)[i];
        int o0 = __ldg(&g_off[d.x]) + __ldg(&g_bpre[d.x >> 10]);
        int o1 = __ldg(&g_off[d.y]) + __ldg(&g_bpre[d.y >> 10]);
        int o2 = __ldg(&g_off[d.z]) + __ldg(&g_bpre[d.z >> 10]);
        int o3 = __ldg(&g_off[d.w]) + __ldg(&g_bpre[d.w >> 10]);
        g_esrc[o0 + atomicAdd(&g_cur[d.x], 1)] = s.x;
        g_esrc[o1 + atomicAdd(&g_cur[d.y], 1)] = s.y;
        g_esrc[o2 + atomicAdd(&g_cur[d.z], 1)] = s.z;
        g_esrc[o3 + atomicAdd(&g_cur[d.w], 1)] = s.w;
    }
}

__device__ __forceinline__ int node_off(int v) {
    return g_off[v] + g_bpre[v >> 10];
}

// ---------------- compensated tensor GEMM helpers ----------------
__device__ __forceinline__ void mma16816(float c[4],
    unsigned a0, unsigned a1, unsigned a2, unsigned a3,
    unsigned b0, unsigned b1)
{
    asm volatile(
        "mma.sync.aligned.m16n8k16.row.col.f32.f16.f16.f32 "
        "{%0,%1,%2,%3}, {%4,%5,%6,%7}, {%8,%9}, {%0,%1,%2,%3};"
        : "+f"(c[0]), "+f"(c[1]), "+f"(c[2]), "+f"(c[3])
        : "r"(a0), "r"(a1), "r"(a2), "r"(a3), "r"(b0), "r"(b1));
}

__device__ __forceinline__ void split_h(float v, __half& hi, __half& lo) {
    hi = __float2half_rn(v);
    lo = __float2half_rn(v - __half2float(hi));
}

__device__ __forceinline__ void fill_w_split_t(
    __half* wt_hi, __half* wt_lo, const float* __restrict__ W, int tid)
{
    #pragma unroll
    for (int q = 0; q < 16; q++) {
        int lin = tid + q * 256;
        int k = lin >> 6, n = lin & 63;
        __half hi, lo;
        split_h(W[lin], hi, lo);
        wt_hi[n * HS + k] = hi;
        wt_lo[n * HS + k] = lo;
    }
}

__device__ __forceinline__ void fill_x_split(
    __half* x_hi, __half* x_lo, const float* __restrict__ x, int row0, int tid,
    const float* scb, const float* shb)
{
    #pragma unroll
    for (int q = 0; q < 4; q++) {
        int lin = tid + q * 256;
        int r = lin >> 4;
        int c4 = (lin & 15) * 4;
        float4 v = make_float4(0.f, 0.f, 0.f, 0.f);
        if (row0 + r < NN) v = *(const float4*)(x + (size_t)(row0 + r) * 64 + c4);
        float o0 = v.x * scb[c4 + 0] + shb[c4 + 0];
        float o1 = v.y * scb[c4 + 1] + shb[c4 + 1];
        float o2 = v.z * scb[c4 + 2] + shb[c4 + 2];
        float o3 = v.w * scb[c4 + 3] + shb[c4 + 3];
        __half h0, l0, h1, l1, h2, l2, h3, l3;
        split_h(o0, h0, l0); split_h(o1, h1, l1);
        split_h(o2, h2, l2); split_h(o3, h3, l3);
        __half* ph = x_hi + (size_t)r * HS + c4;
        __half* pl = x_lo + (size_t)r * HS + c4;
        ph[0] = h0; ph[1] = h1; ph[2] = h2; ph[3] = h3;
        pl[0] = l0; pl[1] = l1; pl[2] = l2; pl[3] = l3;
    }
}

__device__ __forceinline__ void gemm_comp(
    const __half* x_hi, const __half* x_lo,
    const __half* wt_hi, const __half* wt_lo,
    int rowA, int cg, int g, int tig, float c[4][4])
{
    #pragma unroll
    for (int k0 = 0; k0 < 64; k0 += 16) {
        int ka = k0 + tig * 2;
        unsigned ah0 = *(const unsigned*)&x_hi[(rowA + g) * HS + ka];
        unsigned ah1 = *(const unsigned*)&x_hi[(rowA + g + 8) * HS + ka];
        unsigned ah2 = *(const unsigned*)&x_hi[(rowA + g) * HS + ka + 8];
        unsigned ah3 = *(const unsigned*)&x_hi[(rowA + g + 8) * HS + ka + 8];
        unsigned al0 = *(const unsigned*)&x_lo[(rowA + g) * HS + ka];
        unsigned al1 = *(const unsigned*)&x_lo[(rowA + g + 8) * HS + ka];
        unsigned al2 = *(const unsigned*)&x_lo[(rowA + g) * HS + ka + 8];
        unsigned al3 = *(const unsigned*)&x_lo[(rowA + g + 8) * HS + ka + 8];
        #pragma unroll
        for (int nt = 0; nt < 4; nt++) {
            int n = cg * 32 + nt * 8 + g;
            unsigned bh0 = *(const unsigned*)&wt_hi[n * HS + ka];
            unsigned bh1 = *(const unsigned*)&wt_hi[n * HS + ka + 8];
            unsigned bl0 = *(const unsigned*)&wt_lo[n * HS + ka];
            unsigned bl1 = *(const unsigned*)&wt_lo[n * HS + ka + 8];
            mma16816(c[nt], ah0, ah1, ah2, ah3, bh0, bh1);
            mma16816(c[nt], ah0, ah1, ah2, ah3, bl0, bl1);
            mma16816(c[nt], al0, al1, al2, al3, bh0, bh1);
        }
    }
}

// ---- fused layer: gather raw fp16 x -> BN-corrected agg (split);
//      main GEMM agg@W + residual GEMM BN(x)@rW (compensated tensor); epilogue. ----
__global__ __launch_bounds__(256) void k_layer(
    const float* __restrict__ x, const __half* __restrict__ xh,
    const float* __restrict__ stats, const float* __restrict__ gamma, const float* __restrict__ beta,
    const float* __restrict__ W, const float* __restrict__ bias,
    const float* __restrict__ rW, const float* __restrict__ rb,
    float* __restrict__ outh, __half* __restrict__ outh_h,
    float* __restrict__ stats_out)
{
    extern __shared__ __half buf[];
    __half* x_hi  = buf;                 // later aliased by agg_hi
    __half* x_lo  = buf + TILE_H;        // later aliased by agg_lo
    __half* wt_hi = buf + 2 * TILE_H;
    __half* wt_lo = buf + 3 * TILE_H;
    __half* rt_hi = buf + 4 * TILE_H;
    __half* rt_lo = buf + 5 * TILE_H;
    __shared__ float scb[64], shb[64];
    __shared__ float s_sum[64], s_sq[64];
    int tid = threadIdx.x;
    int lane = tid & 31, wi = tid >> 5;

    if (tid < 64) {
        float sc = 1.f, sh = 0.f;
        if (stats) {
            float mu  = stats[tid] * (1.f / NN);
            float var = stats[64 + tid] * (1.f / NN) - mu * mu;
            float rs  = rsqrtf(var + EPS);
            sc = gamma[tid] * rs;
            sh = beta[tid] - mu * sc;
        }
        scb[tid] = sc; shb[tid] = sh;
        s_sum[tid] = 0.f; s_sq[tid] = 0.f;
    }
    fill_w_split_t(wt_hi, wt_lo, W, tid);
    fill_w_split_t(rt_hi, rt_lo, rW, tid);
    __syncthreads();

    int row0 = blockIdx.x * 64;
    fill_x_split(x_hi, x_lo, x, row0, tid, scb, shb);
    __syncthreads();

    int g = lane >> 2, tig = lane & 3;
    int rg = wi & 3, cg = wi >> 2;
    int rowA = rg * 16;

    // ---- residual GEMM: cr = BN(x) @ rW ----
    float cr[4][4] = {};
    gemm_comp(x_hi, x_lo, rt_hi, rt_lo, rowA, cg, g, tig, cr);
    __syncthreads();   // x tiles dead; agg splits may overwrite

    // ---- gather: quarter-warp, 16-edge chunks (2 idx vectors in flight) ----
    {
        const uint4* m8 = (const uint4*)xh;
        int lane8 = lane & 7;
        int qb    = lane & 24;
        for (int t = 0; t < 2; t++) {
            int r = wi * 8 + t * 4 + (qb >> 3);
            int v = row0 + r;
            float a0 = 0.f, a1 = 0.f, a2 = 0.f, a3 = 0.f;
            float a4 = 0.f, a5 = 0.f, a6 = 0.f, a7 = 0.f;
            int s = 0, cnt = 0;
            if (v < NN) {
                s = node_off(v);
                int e = (v + 1 < NN) ? node_off(v + 1) : EE;
                cnt = e - s;
            }
            int m = max(cnt, __shfl_xor_sync(0xffffffffu, cnt, 8));
            int iters = max(m, __shfl_xor_sync(0xffffffffu, m, 16));
            for (int base = 0; base < iters; base += 16) {
                int my0 = base + lane8;
                int my1 = base + 8 + lane8;
                int idx0 = (my0 < cnt) ? __ldg(&g_esrc[s + my0]) : -1;
                int idx1 = (my1 < cnt) ? __ldg(&g_esrc[s + my1]) : -1;
                #pragma unroll
                for (int half = 0; half < 2; half++) {
                    int idxh = half ? idx1 : idx0;
                    #pragma unroll
                    for (int gg = 0; gg < 8; gg += 4) {
                        int s0 = __shfl_sync(0xffffffffu, idxh, qb + gg + 0);
                        int s1 = __shfl_sync(0xffffffffu, idxh, qb + gg + 1);
                        int s2 = __shfl_sync(0xffffffffu, idxh, qb + gg + 2);
                        int s3 = __shfl_sync(0xffffffffu, idxh, qb + gg + 3);
                        uint4 z = make_uint4(0u, 0u, 0u, 0u);
                        uint4 q0 = (s0 >= 0) ? __ldg(&m8[(size_t)s0 * 8 + lane8]) : z;
                        uint4 q1 = (s1 >= 0) ? __ldg(&m8[(size_t)s1 * 8 + lane8]) : z;
                        uint4 q2 = (s2 >= 0) ? __ldg(&m8[(size_t)s2 * 8 + lane8]) : z;
                        uint4 q3 = (s3 >= 0) ? __ldg(&m8[(size_t)s3 * 8 + lane8]) : z;
                        float2 f0, f1, f2, f3;
                        f0 = __half22float2(*(__half2*)&q0.x); f1 = __half22float2(*(__half2*)&q1.x);
                        f2 = __half22float2(*(__half2*)&q2.x); f3 = __half22float2(*(__half2*)&q3.x);
                        a0 += (f0.x + f1.x) + (f2.x + f3.x);
                        a1 += (f0.y + f1.y) + (f2.y + f3.y);
                        f0 = __half22float2(*(__half2*)&q0.y); f1 = __half22float2(*(__half2*)&q1.y);
                        f2 = __half22float2(*(__half2*)&q2.y); f3 = __half22float2(*(__half2*)&q3.y);
                        a2 += (f0.x + f1.x) + (f2.x + f3.x);
                        a3 += (f0.y + f1.y) + (f2.y + f3.y);
                        f0 = __half22float2(*(__half2*)&q0.z); f1 = __half22float2(*(__half2*)&q1.z);
                        f2 = __half22float2(*(__half2*)&q2.z); f3 = __half22float2(*(__half2*)&q3.z);
                        a4 += (f0.x + f1.x) + (f2.x + f3.x);
                        a5 += (f0.y + f1.y) + (f2.y + f3.y);
                        f0 = __half22float2(*(__half2*)&q0.w); f1 = __half22float2(*(__half2*)&q1.w);
                        f2 = __half22float2(*(__half2*)&q2.w); f3 = __half22float2(*(__half2*)&q3.w);
                        a6 += (f0.x + f1.x) + (f2.x + f3.x);
                        a7 += (f0.y + f1.y) + (f2.y + f3.y);
                    }
                }
            }
            if (v < NN) {
                int cb = lane8 * 8;
                float dc = (float)cnt;
                float vals[8] = {a0, a1, a2, a3, a4, a5, a6, a7};
                __half his[8], los[8];
                #pragma unroll
                for (int j = 0; j < 8; j++) {
                    float vv = vals[j] * scb[cb + j] + dc * shb[cb + j];
                    split_h(vv, his[j], los[j]);
                }
                __half* ph = x_hi + (size_t)r * HS + cb;   // agg_hi alias
                __half* pl = x_lo + (size_t)r * HS + cb;   // agg_lo alias
                #pragma unroll
                for (int j = 0; j < 8; j += 2) {
                    __half2 h2v = __halves2half2(his[j], his[j + 1]);
                    __half2 l2v = __halves2half2(los[j], los[j + 1]);
                    *(unsigned*)&ph[j] = *(unsigned*)&h2v;
                    *(unsigned*)&pl[j] = *(unsigned*)&l2v;
                }
            }
        }
    }
    __syncthreads();

    // ---- main GEMM: cm = agg_norm @ W ----
    float cm[4][4] = {};
    gemm_comp(x_hi, x_lo, wt_hi, wt_lo, rowA, cg, g, tig, cm);

    // ---- epilogue in fragment layout; stats via g-lane shfl reduction ----
    #pragma unroll
    for (int nt = 0; nt < 4; nt++) {
        int n = cg * 32 + nt * 8 + tig * 2;
        float bx  = __ldg(&bias[n]),  by  = __ldg(&bias[n + 1]);
        float rbx = __ldg(&rb[n]),    rby = __ldg(&rb[n + 1]);
        float ls0 = 0.f, ls1 = 0.f, lq0 = 0.f, lq1 = 0.f;
        int rA = row0 + rowA + g;
        if (rA < NN) {
            float h0 = fmaxf(cm[nt][0] + bx, 0.f) + fmaxf(cr[nt][0] + rbx, 0.f);
            float h1 = fmaxf(cm[nt][1] + by, 0.f) + fmaxf(cr[nt][1] + rby, 0.f);
            *(float2*)(outh + (size_t)rA * 64 + n) = make_float2(h0, h1);
            if (outh_h) {
                __half2 hh = __floats2half2_rn(h0, h1);
                *(unsigned*)&outh_h[(size_t)rA * 64 + n] = *(unsigned*)&hh;
            }
            ls0 += h0; lq0 += h0 * h0; ls1 += h1; lq1 += h1 * h1;
        }
        int rB = rA + 8;
        if (rB < NN) {
            float h0 = fmaxf(cm[nt][2] + bx, 0.f) + fmaxf(cr[nt][2] + rbx, 0.f);
            float h1 = fmaxf(cm[nt][3] + by, 0.f) + fmaxf(cr[nt][3] + rby, 0.f);
            *(float2*)(outh + (size_t)rB * 64 + n) = make_float2(h0, h1);
            if (outh_h) {
                __half2 hh = __floats2half2_rn(h0, h1);
                *(unsigned*)&outh_h[(size_t)rB * 64 + n] = *(unsigned*)&hh;
            }
            ls0 += h0; lq0 += h0 * h0; ls1 += h1; lq1 += h1 * h1;
        }
        #pragma unroll
        for (int o = 16; o >= 4; o >>= 1) {
            ls0 += __shfl_down_sync(0xffffffffu, ls0, o);
            ls1 += __shfl_down_sync(0xffffffffu, ls1, o);
            lq0 += __shfl_down_sync(0xffffffffu, lq0, o);
            lq1 += __shfl_down_sync(0xffffffffu, lq1, o);
        }
        if (g == 0) {
            atomicAdd(&s_sum[n], ls0);
            atomicAdd(&s_sum[n + 1], ls1);
            atomicAdd(&s_sq[n], lq0);
            atomicAdd(&s_sq[n + 1], lq1);
        }
    }
    __syncthreads();
    if (tid < 64) {
        atomicAdd(&stats_out[tid], s_sum[tid]);
        atomicAdd(&stats_out[64 + tid], s_sq[tid]);
    }
}

// ---------------- atom weights ----------------
__global__ __launch_bounds__(256) void k_wts(
    const float* __restrict__ gamma, const float* __restrict__ beta,
    const float* __restrict__ awW, const float* __restrict__ awb)
{
    int gt = blockIdx.x * blockDim.x + threadIdx.x;
    int v = gt >> 5;
    int lane = gt & 31;
    if (v >= NN) return;
    int f0 = 2 * lane, f1 = f0 + 1;
    float mu0  = g_stats2[f0] * (1.f / NN);
    float var0 = g_stats2[64 + f0] * (1.f / NN) - mu0 * mu0;
    float sc0  = gamma[f0] * rsqrtf(var0 + EPS);
    float sh0  = beta[f0] - mu0 * sc0;
    float mu1  = g_stats2[f1] * (1.f / NN);
    float var1 = g_stats2[64 + f1] * (1.f / NN) - mu1 * mu1;
    float sc1  = gamma[f1] * rsqrtf(var1 + EPS);
    float sh1  = beta[f1] - mu1 * sc1;
    float2 h = ((const float2*)g_h2)[(size_t)v * 32 + lane];
    float p = (h.x * sc0 + sh0) * awW[f0] + (h.y * sc1 + sh1) * awW[f1];
    #pragma unroll
    for (int o = 16; o; o >>= 1) p += __shfl_down_sync(0xffffffffu, p, o);
    if (lane == 0) g_w[v] = 1.f / (1.f + __expf(-(p + awb[0])));
}

// ---------------- pooling ----------------
__global__ __launch_bounds__(64) void k_pool(
    const int* __restrict__ ngr,
    const float* __restrict__ gamma, const float* __restrict__ beta)
{
    int g = blockIdx.x;
    int j = threadIdx.x;
    __shared__ int bnd[2];
    if (j < 2) {
        int key = g + j;
        int lo = 0, hi = NN;
        while (lo < hi) {
            int mid = (lo + hi) >> 1;
            if (ngr[mid] < key) lo = mid + 1; else hi = mid;
        }
        bnd[j] = lo;
    }
    float mu  = g_stats2[j] * (1.f / NN);
    float var = g_stats2[64 + j] * (1.f / NN) - mu * mu;
    float rs  = rsqrtf(var + EPS);
    float sc  = gamma[j] * rs;
    float sh  = beta[j] - mu * sc;
    __syncthreads();

    int s = bnd[0], e = bnd[1];
    float sum = 0.f, mx = -FLT_MAX;
    int n = s;
    for (; n + 4 <= e; n += 4) {
        float h0 = g_h2[(size_t)(n + 0) * 64 + j];
        float h1 = g_h2[(size_t)(n + 1) * 64 + j];
        float h2 = g_h2[(size_t)(n + 2) * 64 + j];
        float h3 = g_h2[(size_t)(n + 3) * 64 + j];
        float w0 = __ldg(&g_w[n + 0]);
        float w1 = __ldg(&g_w[n + 1]);
        float w2 = __ldg(&g_w[n + 2]);
        float w3 = __ldg(&g_w[n + 3]);
        h0 = h0 * sc + sh; h1 = h1 * sc + sh; h2 = h2 * sc + sh; h3 = h3 * sc + sh;
        sum += h0 * w0 + h1 * w1 + h2 * w2 + h3 * w3;
        mx = fmaxf(fmaxf(fmaxf(mx, h0), fmaxf(h1, h2)), h3);
    }
    for (; n < e; n++) {
        float h = g_h2[(size_t)n * 64 + j] * sc + sh;
        sum += h * __ldg(&g_w[n]);
        mx = fmaxf(mx, h);
    }
    g_hg[(size_t)g * 128 + j]      = sum;
    g_hg[(size_t)g * 128 + 64 + j] = mx;
}

// ---------------- classifier layer 1 ----------------
__global__ __launch_bounds__(128) void k_cls1(const float* __restrict__ W, const float* __restrict__ b) {
    __shared__ float xs[8][128];
    int tid = threadIdx.x;
    int row0 = blockIdx.x * 8;
    #pragma unroll
    for (int q = 0; q < 8; q++) {
        int lin = tid + q * 128;
        xs[lin >> 7][lin & 127] = g_hg[(size_t)row0 * 128 + lin];
    }
    __syncthreads();
    int j = tid;
    float acc[8] = {};
    for (int k = 0; k < 128; k++) {
        float w = __ldg(&W[k * 128 + j]);
        #pragma unroll
        for (int r = 0; r < 8; r++) acc[r] += xs[r][k] * w;
    }
    float bj = b[j];
    float lsum = 0.f, lsq = 0.f;
    #pragma unroll
    for (int r = 0; r < 8; r++) {
        float z = fmaxf(acc[r] + bj, 0.f);
        g_z[(size_t)(row0 + r) * 128 + j] = z;
        lsum += z; lsq += z * z;
    }
    atomicAdd(&g_statsC[j], lsum);
    atomicAdd(&g_statsC[128 + j], lsq);
}

// ---------------- classifier layer 2 ----------------
__global__ __launch_bounds__(256) void k_cls2(
    const float* __restrict__ cg, const float* __restrict__ cb,
    const float* __restrict__ W2, const float* __restrict__ b2, float* __restrict__ out)
{
    __shared__ float sc[128], sh[128];
    int tid = threadIdx.x;
    if (tid < 128) {
        float mu  = g_statsC[tid] * (1.f / NG);
        float var = g_statsC[128 + tid] * (1.f / NG) - mu * mu;
        float rs  = rsqrtf(var + EPS);
        float s = cg[tid] * rs;
        sc[tid] = s;
        sh[tid] = cb[tid] - mu * s;
    }
    __syncthreads();
    int idx = blockIdx.x * 256 + tid;
    if (idx >= NG * NT) return;
    int r = idx / NT, t = idx - r * NT;
    float acc = b2[t];
    for (int k = 0; k < 128; k++)
        acc += (g_z[(size_t)r * 128 + k] * sc[k] + sh[k]) * __ldg(&W2[k * NT + t]);
    out[idx] = acc;
}

// ---------------- launch (single stream, graph-capture safe) ----------------
extern "C" void kernel_launch(void* const* d_in, const int* in_sizes, int n_in,
                              void* d_out, int out_size) {
    const float* feats = (const float*)d_in[0];
    const int*   src   = (const int*)d_in[1];
    const int*   dst   = (const int*)d_in[2];
    const int*   ngr   = (const int*)d_in[3];
    const float* W0  = (const float*)d_in[4];
    const float* b0  = (const float*)d_in[5];
    const float* rW0 = (const float*)d_in[6];
    const float* rb0 = (const float*)d_in[7];
    const float* g0  = (const float*)d_in[8];
    const float* be0 = (const float*)d_in[9];
    const float* W1  = (const float*)d_in[10];
    const float* b1  = (const float*)d_in[11];
    const float* rW1 = (const float*)d_in[12];
    const float* rb1 = (const float*)d_in[13];
    const float* g1  = (const float*)d_in[14];
    const float* be1 = (const float*)d_in[15];
    const float* awW = (const float*)d_in[16];
    const float* awb = (const float*)d_in[17];
    const float* c1W = (const float*)d_in[18];
    const float* c1b = (const float*)d_in[19];
    const float* cg  = (const float*)d_in[20];
    const float* cb  = (const float*)d_in[21];
    const float* c2W = (const float*)d_in[22];
    const float* c2b = (const float*)d_in[23];
    float* out = (float*)d_out;

    float *p_h1, *p_h2, *p_s1, *p_s2;
    __half *p_xh, *p_h1h;
    cudaGetSymbolAddress((void**)&p_h1, g_h1);
    cudaGetSymbolAddress((void**)&p_h2, g_h2);
    cudaGetSymbolAddress((void**)&p_s1, g_stats1);
    cudaGetSymbolAddress((void**)&p_s2, g_stats2);
    cudaGetSymbolAddress((void**)&p_xh, g_xh);
    cudaGetSymbolAddress((void**)&p_h1h, g_h1h);

    cudaFuncSetAttribute(k_layer, cudaFuncAttributeMaxDynamicSharedMemorySize, SMEM_L);

    const int GEMM_BLKS = (NN + 63) / 64;
    const int PRE_BLKS  = (NN * FD / 4 + 255) / 256;   // covers both cvt and deg ranges
    const int E4_BLKS   = (EE / 4 + 255) / 256;
    const int WTS_BLKS  = (NN * 32 + 255) / 256;

    // CSR build + feats fp16 conversion (fused)
    k_zero<<<(NN + 256) / 256, 256>>>();
    k_pre<<<PRE_BLKS, 256>>>(feats, p_xh, dst);
    k_scan1<<<NB1, 1024>>>();
    k_scan2<<<1, 128>>>();
    k_scatter<<<E4_BLKS, 256>>>(src, dst);

    // layer 1: gather raw feats (no BN), project + residual (compensated tensor)
    k_layer<<<GEMM_BLKS, 256, SMEM_L>>>(feats, p_xh, nullptr, nullptr, nullptr,
                                        W0, b0, rW0, rb0, p_h1, p_h1h, p_s1);

    // layer 2: gather raw h1, BN1 affine correction, project + residual
    k_layer<<<GEMM_BLKS, 256, SMEM_L>>>(p_h1, p_h1h, p_s1, g0, be0,
                                        W1, b1, rW1, rb1, p_h2, nullptr, p_s2);

    // pooling
    k_wts<<<WTS_BLKS, 256>>>(g1, be1, awW, awb);
    k_pool<<<NG, 64>>>(ngr, g1, be1);

    // classifier head
    k_cls1<<<NG / 8, 128>>>(c1W, c1b);
    k_cls2<<<(NG * NT + 255) / 256, 256>>>(cg, cb, c2W, c2b, out);
}

// round 17
// speedup vs baseline: 1.0310x; 1.0310x over previous
// R17: R15 gather restored (8-edge chunks), k_pre fusion kept, scan2 fused into
//      scan1 via last-block pattern (one fewer serial launch in CSR chain).
#include <cuda_runtime.h>
#include <cuda_fp16.h>
#include <math.h>
#include <float.h>

#define NN 100000
#define EE 1200000
#define FD 64
#define NG 1024
#define NT 12
#define CHID 128
#define EPS 1e-5f
#define NB1 98   // (NN+1023)/1024

#define HS 72                    // half-tile row stride (halves)
#define TILE_H (64 * HS)         // halves per tile
#define SMEM_L (6 * TILE_H * 2)  // 6 half-tiles = 55296 B dynamic smem

// ---------------- scratch ----------------
__device__ __half g_xh[(size_t)NN * FD];   // fp16 feats (layer-1 gather source)
__device__ __half g_h1h[(size_t)NN * FD];  // fp16 h1 (layer-2 gather source)
__device__ float g_h1[(size_t)NN * FD];
__device__ float g_h2[(size_t)NN * FD];
__device__ float g_w[NN];
__device__ int   g_deg[NN + 1];
__device__ int   g_off[NN + 1];
__device__ int   g_cur[NN];
__device__ int   g_esrc[EE];
__device__ int   g_bsum[128];
__device__ int   g_bpre[128];
__device__ int   g_sctr;                   // scan completion counter
__device__ float g_stats1[2 * FD];
__device__ float g_stats2[2 * FD];
__device__ float g_statsC[2 * CHID];
__device__ float g_hg[(size_t)NG * 2 * FD];
__device__ float g_z[(size_t)NG * CHID];

// ---------------- zero ----------------
__global__ void k_zero() {
    int i = blockIdx.x * blockDim.x + threadIdx.x;
    if (i < NN + 1) g_deg[i] = 0;
    if (i < NN) g_cur[i] = 0;
    if (i < 2 * FD) { g_stats1[i] = 0.f; g_stats2[i] = 0.f; }
    if (i < 2 * CHID) g_statsC[i] = 0.f;
    if (i == 0) g_sctr = 0;
}

// ---------------- fused prologue: feats->fp16 convert + degree count ----------------
__global__ void k_pre(const float* __restrict__ x, __half* __restrict__ o,
                      const int* __restrict__ dst) {
    int i = blockIdx.x * blockDim.x + threadIdx.x;
    if (i < NN * FD / 4) {
        float4 v = ((const float4*)x)[i];
        __half2 a = __floats2half2_rn(v.x, v.y);
        __half2 b = __floats2half2_rn(v.z, v.w);
        ((uint2*)o)[i] = make_uint2(*(unsigned*)&a, *(unsigned*)&b);
    }
    if (i < EE / 4) {
        int4 d = ((const int4*)dst)[i];
        atomicAdd(&g_deg[d.x], 1);
        atomicAdd(&g_deg[d.y], 1);
        atomicAdd(&g_deg[d.z], 1);
        atomicAdd(&g_deg[d.w], 1);
    }
}

// ---- scan1 + fused block-sum scan (last-block pattern) ----
__global__ __launch_bounds__(1024) void k_scan1() {
    int tid = threadIdx.x;
    int i = blockIdx.x * 1024 + tid;
    int d = (i < NN) ? g_deg[i] : 0;
    int lane = tid & 31, wid = tid >> 5;
    int v = d;
    #pragma unroll
    for (int o = 1; o < 32; o <<= 1) {
        int t = __shfl_up_sync(0xffffffffu, v, o);
        if (lane >= o) v += t;
    }
    __shared__ int ws[32];
    __shared__ int is_last;
    if (lane == 31) ws[wid] = v;
    __syncthreads();
    if (wid == 0) {
        int u = ws[lane];
        #pragma unroll
        for (int o = 1; o < 32; o <<= 1) {
            int t = __shfl_up_sync(0xffffffffu, u, o);
            if (lane >= o) u += t;
        }
        ws[lane] = u;
    }
    __syncthreads();
    int base = wid ? ws[wid - 1] : 0;
    if (i < NN) g_off[i] = base + v - d;
    if (tid == 0) {
        g_bsum[blockIdx.x] = ws[31];
        __threadfence();
        int prev = atomicAdd(&g_sctr, 1);
        is_last = (prev == NB1 - 1);
    }
    __syncthreads();
    // last block scans the 98 block sums -> g_bpre (exclusive)
    if (is_last && wid == 0) {
        int bv = (lane < NB1) ? g_bsum[lane] : 0;          // lanes 0..31
        int bv2 = (32 + lane < NB1) ? g_bsum[32 + lane] : 0;
        int bv3 = (64 + lane < NB1) ? g_bsum[64 + lane] : 0;
        int bv4 = (96 + lane < NB1) ? g_bsum[96 + lane] : 0;
        // sequential 4-segment warp scan
        int x1 = bv;
        #pragma unroll
        for (int o = 1; o < 32; o <<= 1) {
            int t = __shfl_up_sync(0xffffffffu, x1, o);
            if (lane >= o) x1 += t;
        }
        int s1 = __shfl_sync(0xffffffffu, x1, 31);
        int x2 = bv2;
        #pragma unroll
        for (int o = 1; o < 32; o <<= 1) {
            int t = __shfl_up_sync(0xffffffffu, x2, o);
            if (lane >= o) x2 += t;
        }
        int s2 = __shfl_sync(0xffffffffu, x2, 31);
        int x3 = bv3;
        #pragma unroll
        for (int o = 1; o < 32; o <<= 1) {
            int t = __shfl_up_sync(0xffffffffu, x3, o);
            if (lane >= o) x3 += t;
        }
        int s3 = __shfl_sync(0xffffffffu, x3, 31);
        int x4 = bv4;
        #pragma unroll
        for (int o = 1; o < 32; o <<= 1) {
            int t = __shfl_up_sync(0xffffffffu, x4, o);
            if (lane >= o) x4 += t;
        }
        if (lane < NB1)       g_bpre[lane]      = x1 - bv;
        if (32 + lane < NB1)  g_bpre[32 + lane] = s1 + x2 - bv2;
        if (64 + lane < NB1)  g_bpre[64 + lane] = s1 + s2 + x3 - bv3;
        if (96 + lane < NB1)  g_bpre[96 + lane] = s1 + s2 + s3 + x4 - bv4;
    }
}

__global__ void k_scatter(const int* __restrict__ src, const int* __restrict__ dst) {
    int i = blockIdx.x * blockDim.x + threadIdx.x;
    if (i < EE / 4) {
        int4 s = ((const int4*)src)[i];
        int4 d = ((const int4*)dst)[i];
        int o0 = __ldg(&g_off[d.x]) + __ldg(&g_bpre[d.x >> 10]);
        int o1 = __ldg(&g_off[d.y]) + __ldg(&g_bpre[d.y >> 10]);
        int o2 = __ldg(&g_off[d.z]) + __ldg(&g_bpre[d.z >> 10]);
        int o3 = __ldg(&g_off[d.w]) + __ldg(&g_bpre[d.w >> 10]);
        g_esrc[o0 + atomicAdd(&g_cur[d.x], 1)] = s.x;
        g_esrc[o1 + atomicAdd(&g_cur[d.y], 1)] = s.y;
        g_esrc[o2 + atomicAdd(&g_cur[d.z], 1)] = s.z;
        g_esrc[o3 + atomicAdd(&g_cur[d.w], 1)] = s.w;
    }
}

__device__ __forceinline__ int node_off(int v) {
    return g_off[v] + g_bpre[v >> 10];
}

// ---------------- compensated tensor GEMM helpers ----------------
__device__ __forceinline__ void mma16816(float c[4],
    unsigned a0, unsigned a1, unsigned a2, unsigned a3,
    unsigned b0, unsigned b1)
{
    asm volatile(
        "mma.sync.aligned.m16n8k16.row.col.f32.f16.f16.f32 "
        "{%0,%1,%2,%3}, {%4,%5,%6,%7}, {%8,%9}, {%0,%1,%2,%3};"
        : "+f"(c[0]), "+f"(c[1]), "+f"(c[2]), "+f"(c[3])
        : "r"(a0), "r"(a1), "r"(a2), "r"(a3), "r"(b0), "r"(b1));
}

__device__ __forceinline__ void split_h(float v, __half& hi, __half& lo) {
    hi = __float2half_rn(v);
    lo = __float2half_rn(v - __half2float(hi));
}

__device__ __forceinline__ void fill_w_split_t(
    __half* wt_hi, __half* wt_lo, const float* __restrict__ W, int tid)
{
    #pragma unroll
    for (int q = 0; q < 16; q++) {
        int lin = tid + q * 256;
        int k = lin >> 6, n = lin & 63;
        __half hi, lo;
        split_h(W[lin], hi, lo);
        wt_hi[n * HS + k] = hi;
        wt_lo[n * HS + k] = lo;
    }
}

__device__ __forceinline__ void fill_x_split(
    __half* x_hi, __half* x_lo, const float* __restrict__ x, int row0, int tid,
    const float* scb, const float* shb)
{
    #pragma unroll
    for (int q = 0; q < 4; q++) {
        int lin = tid + q * 256;
        int r = lin >> 4;
        int c4 = (lin & 15) * 4;
        float4 v = make_float4(0.f, 0.f, 0.f, 0.f);
        if (row0 + r < NN) v = *(const float4*)(x + (size_t)(row0 + r) * 64 + c4);
        float o0 = v.x * scb[c4 + 0] + shb[c4 + 0];
        float o1 = v.y * scb[c4 + 1] + shb[c4 + 1];
        float o2 = v.z * scb[c4 + 2] + shb[c4 + 2];
        float o3 = v.w * scb[c4 + 3] + shb[c4 + 3];
        __half h0, l0, h1, l1, h2, l2, h3, l3;
        split_h(o0, h0, l0); split_h(o1, h1, l1);
        split_h(o2, h2, l2); split_h(o3, h3, l3);
        __half* ph = x_hi + (size_t)r * HS + c4;
        __half* pl = x_lo + (size_t)r * HS + c4;
        ph[0] = h0; ph[1] = h1; ph[2] = h2; ph[3] = h3;
        pl[0] = l0; pl[1] = l1; pl[2] = l2; pl[3] = l3;
    }
}

__device__ __forceinline__ void gemm_comp(
    const __half* x_hi, const __half* x_lo,
    const __half* wt_hi, const __half* wt_lo,
    int rowA, int cg, int g, int tig, float c[4][4])
{
    #pragma unroll
    for (int k0 = 0; k0 < 64; k0 += 16) {
        int ka = k0 + tig * 2;
        unsigned ah0 = *(const unsigned*)&x_hi[(rowA + g) * HS + ka];
        unsigned ah1 = *(const unsigned*)&x_hi[(rowA + g + 8) * HS + ka];
        unsigned ah2 = *(const unsigned*)&x_hi[(rowA + g) * HS + ka + 8];
        unsigned ah3 = *(const unsigned*)&x_hi[(rowA + g + 8) * HS + ka + 8];
        unsigned al0 = *(const unsigned*)&x_lo[(rowA + g) * HS + ka];
        unsigned al1 = *(const unsigned*)&x_lo[(rowA + g + 8) * HS + ka];
        unsigned al2 = *(const unsigned*)&x_lo[(rowA + g) * HS + ka + 8];
        unsigned al3 = *(const unsigned*)&x_lo[(rowA + g + 8) * HS + ka + 8];
        #pragma unroll
        for (int nt = 0; nt < 4; nt++) {
            int n = cg * 32 + nt * 8 + g;
            unsigned bh0 = *(const unsigned*)&wt_hi[n * HS + ka];
            unsigned bh1 = *(const unsigned*)&wt_hi[n * HS + ka + 8];
            unsigned bl0 = *(const unsigned*)&wt_lo[n * HS + ka];
            unsigned bl1 = *(const unsigned*)&wt_lo[n * HS + ka + 8];
            mma16816(c[nt], ah0, ah1, ah2, ah3, bh0, bh1);
            mma16816(c[nt], ah0, ah1, ah2, ah3, bl0, bl1);
            mma16816(c[nt], al0, al1, al2, al3, bh0, bh1);
        }
    }
}

// ---- fused layer: gather raw fp16 x -> BN-corrected agg (split);
//      main GEMM agg@W + residual GEMM BN(x)@rW (compensated tensor); epilogue. ----
__global__ __launch_bounds__(256) void k_layer(
    const float* __restrict__ x, const __half* __restrict__ xh,
    const float* __restrict__ stats, const float* __restrict__ gamma, const float* __restrict__ beta,
    const float* __restrict__ W, const float* __restrict__ bias,
    const float* __restrict__ rW, const float* __restrict__ rb,
    float* __restrict__ outh, __half* __restrict__ outh_h,
    float* __restrict__ stats_out)
{
    extern __shared__ __half buf[];
    __half* x_hi  = buf;                 // later aliased by agg_hi
    __half* x_lo  = buf + TILE_H;        // later aliased by agg_lo
    __half* wt_hi = buf + 2 * TILE_H;
    __half* wt_lo = buf + 3 * TILE_H;
    __half* rt_hi = buf + 4 * TILE_H;
    __half* rt_lo = buf + 5 * TILE_H;
    __shared__ float scb[64], shb[64];
    __shared__ float s_sum[64], s_sq[64];
    int tid = threadIdx.x;
    int lane = tid & 31, wi = tid >> 5;

    if (tid < 64) {
        float sc = 1.f, sh = 0.f;
        if (stats) {
            float mu  = stats[tid] * (1.f / NN);
            float var = stats[64 + tid] * (1.f / NN) - mu * mu;
            float rs  = rsqrtf(var + EPS);
            sc = gamma[tid] * rs;
            sh = beta[tid] - mu * sc;
        }
        scb[tid] = sc; shb[tid] = sh;
        s_sum[tid] = 0.f; s_sq[tid] = 0.f;
    }
    fill_w_split_t(wt_hi, wt_lo, W, tid);
    fill_w_split_t(rt_hi, rt_lo, rW, tid);
    __syncthreads();

    int row0 = blockIdx.x * 64;
    fill_x_split(x_hi, x_lo, x, row0, tid, scb, shb);
    __syncthreads();

    int g = lane >> 2, tig = lane & 3;
    int rg = wi & 3, cg = wi >> 2;
    int rowA = rg * 16;

    // ---- residual GEMM: cr = BN(x) @ rW ----
    float cr[4][4] = {};
    gemm_comp(x_hi, x_lo, rt_hi, rt_lo, rowA, cg, g, tig, cr);
    __syncthreads();   // x tiles dead; agg splits may overwrite

    // ---- gather: quarter-warp, 8-edge chunks (R15-proven) ----
    {
        const uint4* m8 = (const uint4*)xh;
        int lane8 = lane & 7;
        int qb    = lane & 24;
        for (int t = 0; t < 2; t++) {
            int r = wi * 8 + t * 4 + (qb >> 3);
            int v = row0 + r;
            float a0 = 0.f, a1 = 0.f, a2 = 0.f, a3 = 0.f;
            float a4 = 0.f, a5 = 0.f, a6 = 0.f, a7 = 0.f;
            int s = 0, cnt = 0;
            if (v < NN) {
                s = node_off(v);
                int e = (v + 1 < NN) ? node_off(v + 1) : EE;
                cnt = e - s;
            }
            int m = max(cnt, __shfl_xor_sync(0xffffffffu, cnt, 8));
            int iters = max(m, __shfl_xor_sync(0xffffffffu, m, 16));
            for (int base = 0; base < iters; base += 8) {
                int my = base + lane8;
                int idx = (my < cnt) ? __ldg(&g_esrc[s + my]) : -1;
                #pragma unroll
                for (int gg = 0; gg < 8; gg += 4) {
                    int s0 = __shfl_sync(0xffffffffu, idx, qb + gg + 0);
                    int s1 = __shfl_sync(0xffffffffu, idx, qb + gg + 1);
                    int s2 = __shfl_sync(0xffffffffu, idx, qb + gg + 2);
                    int s3 = __shfl_sync(0xffffffffu, idx, qb + gg + 3);
                    uint4 z = make_uint4(0u, 0u, 0u, 0u);
                    uint4 q0 = (s0 >= 0) ? __ldg(&m8[(size_t)s0 * 8 + lane8]) : z;
                    uint4 q1 = (s1 >= 0) ? __ldg(&m8[(size_t)s1 * 8 + lane8]) : z;
                    uint4 q2 = (s2 >= 0) ? __ldg(&m8[(size_t)s2 * 8 + lane8]) : z;
                    uint4 q3 = (s3 >= 0) ? __ldg(&m8[(size_t)s3 * 8 + lane8]) : z;
                    float2 f0, f1, f2, f3;
                    f0 = __half22float2(*(__half2*)&q0.x); f1 = __half22float2(*(__half2*)&q1.x);
                    f2 = __half22float2(*(__half2*)&q2.x); f3 = __half22float2(*(__half2*)&q3.x);
                    a0 += (f0.x + f1.x) + (f2.x + f3.x);
                    a1 += (f0.y + f1.y) + (f2.y + f3.y);
                    f0 = __half22float2(*(__half2*)&q0.y); f1 = __half22float2(*(__half2*)&q1.y);
                    f2 = __half22float2(*(__half2*)&q2.y); f3 = __half22float2(*(__half2*)&q3.y);
                    a2 += (f0.x + f1.x) + (f2.x + f3.x);
                    a3 += (f0.y + f1.y) + (f2.y + f3.y);
                    f0 = __half22float2(*(__half2*)&q0.z); f1 = __half22float2(*(__half2*)&q1.z);
                    f2 = __half22float2(*(__half2*)&q2.z); f3 = __half22float2(*(__half2*)&q3.z);
                    a4 += (f0.x + f1.x) + (f2.x + f3.x);
                    a5 += (f0.y + f1.y) + (f2.y + f3.y);
                    f0 = __half22float2(*(__half2*)&q0.w); f1 = __half22float2(*(__half2*)&q1.w);
                    f2 = __half22float2(*(__half2*)&q2.w); f3 = __half22float2(*(__half2*)&q3.w);
                    a6 += (f0.x + f1.x) + (f2.x + f3.x);
                    a7 += (f0.y + f1.y) + (f2.y + f3.y);
                }
            }
            if (v < NN) {
                int cb = lane8 * 8;
                float dc = (float)cnt;
                float vals[8] = {a0, a1, a2, a3, a4, a5, a6, a7};
                __half his[8], los[8];
                #pragma unroll
                for (int j = 0; j < 8; j++) {
                    float vv = vals[j] * scb[cb + j] + dc * shb[cb + j];
                    split_h(vv, his[j], los[j]);
                }
                __half* ph = x_hi + (size_t)r * HS + cb;   // agg_hi alias
                __half* pl = x_lo + (size_t)r * HS + cb;   // agg_lo alias
                #pragma unroll
                for (int j = 0; j < 8; j += 2) {
                    __half2 h2v = __halves2half2(his[j], his[j + 1]);
                    __half2 l2v = __halves2half2(los[j], los[j + 1]);
                    *(unsigned*)&ph[j] = *(unsigned*)&h2v;
                    *(unsigned*)&pl[j] = *(unsigned*)&l2v;
                }
            }
        }
    }
    __syncthreads();

    // ---- main GEMM: cm = agg_norm @ W ----
    float cm[4][4] = {};
    gemm_comp(x_hi, x_lo, wt_hi, wt_lo, rowA, cg, g, tig, cm);

    // ---- epilogue in fragment layout; stats via g-lane shfl reduction ----
    #pragma unroll
    for (int nt = 0; nt < 4; nt++) {
        int n = cg * 32 + nt * 8 + tig * 2;
        float bx  = __ldg(&bias[n]),  by  = __ldg(&bias[n + 1]);
        float rbx = __ldg(&rb[n]),    rby = __ldg(&rb[n + 1]);
        float ls0 = 0.f, ls1 = 0.f, lq0 = 0.f, lq1 = 0.f;
        int rA = row0 + rowA + g;
        if (rA < NN) {
            float h0 = fmaxf(cm[nt][0] + bx, 0.f) + fmaxf(cr[nt][0] + rbx, 0.f);
            float h1 = fmaxf(cm[nt][1] + by, 0.f) + fmaxf(cr[nt][1] + rby, 0.f);
            *(float2*)(outh + (size_t)rA * 64 + n) = make_float2(h0, h1);
            if (outh_h) {
                __half2 hh = __floats2half2_rn(h0, h1);
                *(unsigned*)&outh_h[(size_t)rA * 64 + n] = *(unsigned*)&hh;
            }
            ls0 += h0; lq0 += h0 * h0; ls1 += h1; lq1 += h1 * h1;
        }
        int rB = rA + 8;
        if (rB < NN) {
            float h0 = fmaxf(cm[nt][2] + bx, 0.f) + fmaxf(cr[nt][2] + rbx, 0.f);
            float h1 = fmaxf(cm[nt][3] + by, 0.f) + fmaxf(cr[nt][3] + rby, 0.f);
            *(float2*)(outh + (size_t)rB * 64 + n) = make_float2(h0, h1);
            if (outh_h) {
                __half2 hh = __floats2half2_rn(h0, h1);
                *(unsigned*)&outh_h[(size_t)rB * 64 + n] = *(unsigned*)&hh;
            }
            ls0 += h0; lq0 += h0 * h0; ls1 += h1; lq1 += h1 * h1;
        }
        #pragma unroll
        for (int o = 16; o >= 4; o >>= 1) {
            ls0 += __shfl_down_sync(0xffffffffu, ls0, o);
            ls1 += __shfl_down_sync(0xffffffffu, ls1, o);
            lq0 += __shfl_down_sync(0xffffffffu, lq0, o);
            lq1 += __shfl_down_sync(0xffffffffu, lq1, o);
        }
        if (g == 0) {
            atomicAdd(&s_sum[n], ls0);
            atomicAdd(&s_sum[n + 1], ls1);
            atomicAdd(&s_sq[n], lq0);
            atomicAdd(&s_sq[n + 1], lq1);
        }
    }
    __syncthreads();
    if (tid < 64) {
        atomicAdd(&stats_out[tid], s_sum[tid]);
        atomicAdd(&stats_out[64 + tid], s_sq[tid]);
    }
}

// ---------------- atom weights ----------------
__global__ __launch_bounds__(256) void k_wts(
    const float* __restrict__ gamma, const float* __restrict__ beta,
    const float* __restrict__ awW, const float* __restrict__ awb)
{
    int gt = blockIdx.x * blockDim.x + threadIdx.x;
    int v = gt >> 5;
    int lane = gt & 31;
    if (v >= NN) return;
    int f0 = 2 * lane, f1 = f0 + 1;
    float mu0  = g_stats2[f0] * (1.f / NN);
    float var0 = g_stats2[64 + f0] * (1.f / NN) - mu0 * mu0;
    float sc0  = gamma[f0] * rsqrtf(var0 + EPS);
    float sh0  = beta[f0] - mu0 * sc0;
    float mu1  = g_stats2[f1] * (1.f / NN);
    float var1 = g_stats2[64 + f1] * (1.f / NN) - mu1 * mu1;
    float sc1  = gamma[f1] * rsqrtf(var1 + EPS);
    float sh1  = beta[f1] - mu1 * sc1;
    float2 h = ((const float2*)g_h2)[(size_t)v * 32 + lane];
    float p = (h.x * sc0 + sh0) * awW[f0] + (h.y * sc1 + sh1) * awW[f1];
    #pragma unroll
    for (int o = 16; o; o >>= 1) p += __shfl_down_sync(0xffffffffu, p, o);
    if (lane == 0) g_w[v] = 1.f / (1.f + __expf(-(p + awb[0])));
}

// ---------------- pooling ----------------
__global__ __launch_bounds__(64) void k_pool(
    const int* __restrict__ ngr,
    const float* __restrict__ gamma, const float* __restrict__ beta)
{
    int g = blockIdx.x;
    int j = threadIdx.x;
    __shared__ int bnd[2];
    if (j < 2) {
        int key = g + j;
        int lo = 0, hi = NN;
        while (lo < hi) {
            int mid = (lo + hi) >> 1;
            if (ngr[mid] < key) lo = mid + 1; else hi = mid;
        }
        bnd[j] = lo;
    }
    float mu  = g_stats2[j] * (1.f / NN);
    float var = g_stats2[64 + j] * (1.f / NN) - mu * mu;
    float rs  = rsqrtf(var + EPS);
    float sc  = gamma[j] * rs;
    float sh  = beta[j] - mu * sc;
    __syncthreads();

    int s = bnd[0], e = bnd[1];
    float sum = 0.f, mx = -FLT_MAX;
    int n = s;
    for (; n + 4 <= e; n += 4) {
        float h0 = g_h2[(size_t)(n + 0) * 64 + j];
        float h1 = g_h2[(size_t)(n + 1) * 64 + j];
        float h2 = g_h2[(size_t)(n + 2) * 64 + j];
        float h3 = g_h2[(size_t)(n + 3) * 64 + j];
        float w0 = __ldg(&g_w[n + 0]);
        float w1 = __ldg(&g_w[n + 1]);
        float w2 = __ldg(&g_w[n + 2]);
        float w3 = __ldg(&g_w[n + 3]);
        h0 = h0 * sc + sh; h1 = h1 * sc + sh; h2 = h2 * sc + sh; h3 = h3 * sc + sh;
        sum += h0 * w0 + h1 * w1 + h2 * w2 + h3 * w3;
        mx = fmaxf(fmaxf(fmaxf(mx, h0), fmaxf(h1, h2)), h3);
    }
    for (; n < e; n++) {
        float h = g_h2[(size_t)n * 64 + j] * sc + sh;
        sum += h * __ldg(&g_w[n]);
        mx = fmaxf(mx, h);
    }
    g_hg[(size_t)g * 128 + j]      = sum;
    g_hg[(size_t)g * 128 + 64 + j] = mx;
}

// ---------------- classifier layer 1 ----------------
__global__ __launch_bounds__(128) void k_cls1(const float* __restrict__ W, const float* __restrict__ b) {
    __shared__ float xs[8][128];
    int tid = threadIdx.x;
    int row0 = blockIdx.x * 8;
    #pragma unroll
    for (int q = 0; q < 8; q++) {
        int lin = tid + q * 128;
        xs[lin >> 7][lin & 127] = g_hg[(size_t)row0 * 128 + lin];
    }
    __syncthreads();
    int j = tid;
    float acc[8] = {};
    for (int k = 0; k < 128; k++) {
        float w = __ldg(&W[k * 128 + j]);
        #pragma unroll
        for (int r = 0; r < 8; r++) acc[r] += xs[r][k] * w;
    }
    float bj = b[j];
    float lsum = 0.f, lsq = 0.f;
    #pragma unroll
    for (int r = 0; r < 8; r++) {
        float z = fmaxf(acc[r] + bj, 0.f);
        g_z[(size_t)(row0 + r) * 128 + j] = z;
        lsum += z; lsq += z * z;
    }
    atomicAdd(&g_statsC[j], lsum);
    atomicAdd(&g_statsC[128 + j], lsq);
}

// ---------------- classifier layer 2 ----------------
__global__ __launch_bounds__(256) void k_cls2(
    const float* __restrict__ cg, const float* __restrict__ cb,
    const float* __restrict__ W2, const float* __restrict__ b2, float* __restrict__ out)
{
    __shared__ float sc[128], sh[128];
    int tid = threadIdx.x;
    if (tid < 128) {
        float mu  = g_statsC[tid] * (1.f / NG);
        float var = g_statsC[128 + tid] * (1.f / NG) - mu * mu;
        float rs  = rsqrtf(var + EPS);
        float s = cg[tid] * rs;
        sc[tid] = s;
        sh[tid] = cb[tid] - mu * s;
    }
    __syncthreads();
    int idx = blockIdx.x * 256 + tid;
    if (idx >= NG * NT) return;
    int r = idx / NT, t = idx - r * NT;
    float acc = b2[t];
    for (int k = 0; k < 128; k++)
        acc += (g_z[(size_t)r * 128 + k] * sc[k] + sh[k]) * __ldg(&W2[k * NT + t]);
    out[idx] = acc;
}

// ---------------- launch (single stream, graph-capture safe) ----------------
extern "C" void kernel_launch(void* const* d_in, const int* in_sizes, int n_in,
                              void* d_out, int out_size) {
    const float* feats = (const float*)d_in[0];
    const int*   src   = (const int*)d_in[1];
    const int*   dst   = (const int*)d_in[2];
    const int*   ngr   = (const int*)d_in[3];
    const float* W0  = (const float*)d_in[4];
    const float* b0  = (const float*)d_in[5];
    const float* rW0 = (const float*)d_in[6];
    const float* rb0 = (const float*)d_in[7];
    const float* g0  = (const float*)d_in[8];
    const float* be0 = (const float*)d_in[9];
    const float* W1  = (const float*)d_in[10];
    const float* b1  = (const float*)d_in[11];
    const float* rW1 = (const float*)d_in[12];
    const float* rb1 = (const float*)d_in[13];
    const float* g1  = (const float*)d_in[14];
    const float* be1 = (const float*)d_in[15];
    const float* awW = (const float*)d_in[16];
    const float* awb = (const float*)d_in[17];
    const float* c1W = (const float*)d_in[18];
    const float* c1b = (const float*)d_in[19];
    const float* cg  = (const float*)d_in[20];
    const float* cb  = (const float*)d_in[21];
    const float* c2W = (const float*)d_in[22];
    const float* c2b = (const float*)d_in[23];
    float* out = (float*)d_out;

    float *p_h1, *p_h2, *p_s1, *p_s2;
    __half *p_xh, *p_h1h;
    cudaGetSymbolAddress((void**)&p_h1, g_h1);
    cudaGetSymbolAddress((void**)&p_h2, g_h2);
    cudaGetSymbolAddress((void**)&p_s1, g_stats1);
    cudaGetSymbolAddress((void**)&p_s2, g_stats2);
    cudaGetSymbolAddress((void**)&p_xh, g_xh);
    cudaGetSymbolAddress((void**)&p_h1h, g_h1h);

    cudaFuncSetAttribute(k_layer, cudaFuncAttributeMaxDynamicSharedMemorySize, SMEM_L);

    const int GEMM_BLKS = (NN + 63) / 64;
    const int PRE_BLKS  = (NN * FD / 4 + 255) / 256;   // covers both cvt and deg ranges
    const int E4_BLKS   = (EE / 4 + 255) / 256;
    const int WTS_BLKS  = (NN * 32 + 255) / 256;

    // CSR build + feats fp16 conversion (fused); scan2 fused into scan1
    k_zero<<<(NN + 256) / 256, 256>>>();
    k_pre<<<PRE_BLKS, 256>>>(feats, p_xh, dst);
    k_scan1<<<NB1, 1024>>>();
    k_scatter<<<E4_BLKS, 256>>>(src, dst);

    // layer 1: gather raw feats (no BN), project + residual (compensated tensor)
    k_layer<<<GEMM_BLKS, 256, SMEM_L>>>(feats, p_xh, nullptr, nullptr, nullptr,
                                        W0, b0, rW0, rb0, p_h1, p_h1h, p_s1);

    // layer 2: gather raw h1, BN1 affine correction, project + residual
    k_layer<<<GEMM_BLKS, 256, SMEM_L>>>(p_h1, p_h1h, p_s1, g0, be0,
                                        W1, b1, rW1, rb1, p_h2, nullptr, p_s2);

    // pooling
    k_wts<<<WTS_BLKS, 256>>>(g1, be1, awW, awb);
    k_pool<<<NG, 64>>>(ngr, g1, be1);

    // classifier head
    k_cls1<<<NG / 8, 128>>>(c1W, c1b);
    k_cls2<<<(NG * NT + 255) / 256, 256>>>(cg, cb, c2W, c2b, out);
}